// round 16
// baseline (speedup 1.0000x reference)
#include <cuda_runtime.h>
#include <cuda_fp16.h>
#include <cstdint>

#define DIM     64
#define NMAX    262144
#define NLMAX   1024
#define TAU     0.3f
#define UPITCH  36          // uints per f16 tile row: 32 data + 4 pad (bank-clean)

__device__ float g_csq[NLMAX];
__device__ int   g_ncand;
__device__ int   g_nfull;
__device__ int4  g_cand[NMAX];   // (row, i1, i2, unused)
__device__ int   g_full[NMAX];

typedef unsigned long long u64;

// Packed fp32x2 FMA (FFMA2) for the exact full-rescue pass.
__device__ __forceinline__ u64 ffma2(u64 a, u64 b, u64 c) {
    u64 d;
    asm("fma.rn.f32x2 %0, %1, %2, %3;" : "=l"(d) : "l"(a), "l"(b), "l"(c));
    return d;
}
__device__ __forceinline__ float2 unpack2(u64 v) {
    float2 f;
    asm("mov.b64 {%0, %1}, %2;" : "=f"(f.x), "=f"(f.y) : "l"(v));
    return f;
}

// fp16 tensor-core MMA, m16n8k16 with fp32 accumulate.
__device__ __forceinline__ void mma_f16(float c[4], const uint32_t a[4],
                                        const uint32_t b[2]) {
    asm volatile(
        "mma.sync.aligned.m16n8k16.row.col.f32.f16.f16.f32 "
        "{%0,%1,%2,%3}, {%4,%5,%6,%7}, {%8,%9}, {%0,%1,%2,%3};"
        : "+f"(c[0]), "+f"(c[1]), "+f"(c[2]), "+f"(c[3])
        : "r"(a[0]), "r"(a[1]), "r"(a[2]), "r"(a[3]), "r"(b[0]), "r"(b[1]));
}

__device__ __forceinline__ uint32_t packhf2(float x, float y) {
    __half2 h = __floats2half2_rn(x, y);
    return *reinterpret_cast<uint32_t*>(&h);
}

// Top-3 insert: keeps (m1,i1),(m2,i2),m3. ci=-1 marks an unknown-index entry
// (from cross-lane m3 merges); classify escalates rows whose i2 is unknown.
__device__ __forceinline__ void ins3(float d, int ci,
                                     float& m1, float& m2, float& m3,
                                     int& i1, int& i2) {
    if (d < m3) {
        if (d < m2) {
            m3 = m2;
            if (d < m1) { m2 = m1; i2 = i1; m1 = d; i1 = ci; }
            else        { m2 = d;  i2 = ci; }
        } else {
            m3 = d;
        }
    }
}

// ---------------------------------------------------------------------------
// Kernel 0: centroid squared norms (warp per row) + counter reset.
// ---------------------------------------------------------------------------
__global__ void csq_kernel(const float* __restrict__ cents) {
    if (blockIdx.x == 0 && threadIdx.x == 0) { g_ncand = 0; g_nfull = 0; }
    int w    = (blockIdx.x * blockDim.x + threadIdx.x) >> 5;
    int lane = threadIdx.x & 31;
    if (w < NLMAX) {
        float2 v = reinterpret_cast<const float2*>(cents + (size_t)w * DIM)[lane];
        float s = v.x * v.x + v.y * v.y;
        #pragma unroll
        for (int off = 16; off > 0; off >>= 1)
            s += __shfl_xor_sync(0xffffffffu, s, off);
        if (lane == 0) g_csq[w] = s;
    }
}

// ---------------------------------------------------------------------------
// Kernel 1: fp16 mma.sync assignment + top-3 margins + fused gather.
// CTA tile M=128, 8 tiles of 128 cents (double-buffered f16 smem), K=64.
// 8 warps as 4(M) x 2(N); warp tile 32x64 -> 2x8 m16n8k16 fragments.
// Ambiguous-but-certified rows -> g_cand (2-way exact check kernel);
// uncertifiable rows -> g_full (tiled exact rescan kernel).
// ---------------------------------------------------------------------------
#define UA_OFF   0
#define UB_OFF   18432               // two buffers of 128*36*4 B
#define SCSQ_OFF 55296
#define RED1_OFF 59392               // float [2][128] m1
#define RED2_OFF 60416               // float [2][128] m2
#define RED3_OFF 61440               // float [2][128] m3
#define REDI1_OFF 62464              // int   [2][128] i1
#define REDI2_OFF 63488              // int   [2][128] i2
#define SBI_OFF  64512               // int   [128]
#define SMEMB    65024

__global__ __launch_bounds__(256, 2)
void assign_mma_kernel(const float* __restrict__ vecs,
                       const float* __restrict__ cents,
                       float* __restrict__ out) {
    extern __shared__ char smem[];
    uint32_t* uA    = reinterpret_cast<uint32_t*>(smem + UA_OFF);
    uint32_t* uB    = reinterpret_cast<uint32_t*>(smem + UB_OFF);
    float*    scsq  = reinterpret_cast<float*>(smem + SCSQ_OFF);
    float*    sred1 = reinterpret_cast<float*>(smem + RED1_OFF);
    float*    sred2 = reinterpret_cast<float*>(smem + RED2_OFF);
    float*    sred3 = reinterpret_cast<float*>(smem + RED3_OFF);
    int*      sri1  = reinterpret_cast<int*>(smem + REDI1_OFF);
    int*      sri2  = reinterpret_cast<int*>(smem + REDI2_OFF);
    int*      sbi   = reinterpret_cast<int*>(smem + SBI_OFF);

    const int tid  = threadIdx.x;
    const int lane = tid & 31;
    const int wid  = tid >> 5;
    const int g    = lane >> 2;
    const int tig  = lane & 3;
    const int moff = (wid >> 1) * 32;
    const int noff = (wid & 1) * 64;
    const int vbase = blockIdx.x * 128;

    // A tile: fp32 -> f16x2, padded rows (UPITCH=36 -> conflict-free frags).
    #pragma unroll
    for (int k = 0; k < 8; k++) {
        int idx = tid + 256 * k;
        int r = idx >> 4, c4 = idx & 15;
        float4 v = reinterpret_cast<const float4*>(vecs)[(size_t)(vbase + r) * 16 + c4];
        uint2 u = make_uint2(packhf2(v.x, v.y), packhf2(v.z, v.w));
        *reinterpret_cast<uint2*>(&uA[r * UPITCH + c4 * 2]) = u;
    }
    float4 pf[8];
    #pragma unroll
    for (int k = 0; k < 8; k++) {
        int idx = tid + 256 * k;
        int r = idx >> 4, c4 = idx & 15;
        pf[k] = reinterpret_cast<const float4*>(cents)[(size_t)r * 16 + c4];
    }
    #pragma unroll
    for (int k = 0; k < 4; k++) scsq[tid + 256 * k] = g_csq[tid + 256 * k];
    #pragma unroll
    for (int k = 0; k < 8; k++) {
        int idx = tid + 256 * k;
        int r = idx >> 4, c4 = idx & 15;
        uint2 u = make_uint2(packhf2(pf[k].x, pf[k].y), packhf2(pf[k].z, pf[k].w));
        *reinterpret_cast<uint2*>(&uB[r * UPITCH + c4 * 2]) = u;
    }
    __syncthreads();

    // Per-thread top-3 for 4 row-slots: s=mt*2+hi -> row moff+mt*16+hi*8+g.
    float m1[4], m2[4], m3[4];
    int   i1[4], i2[4];
    #pragma unroll
    for (int s = 0; s < 4; s++) {
        m1[s] = 3.4e38f; m2[s] = 3.4e38f; m3[s] = 3.4e38f;
        i1[s] = 0; i2[s] = -1;
    }

    for (int t = 0; t < 8; t++) {
        if (t < 7) {   // prefetch next tile (LDG overlaps this tile's MMAs)
            #pragma unroll
            for (int k = 0; k < 8; k++) {
                int idx = tid + 256 * k;
                int r = idx >> 4, c4 = idx & 15;
                pf[k] = reinterpret_cast<const float4*>(cents)
                            [(size_t)((t + 1) * 128 + r) * 16 + c4];
            }
        }

        const uint32_t* sB = uB + (t & 1) * (128 * UPITCH);

        float c[2][8][4];
        #pragma unroll
        for (int mt = 0; mt < 2; mt++)
            #pragma unroll
            for (int nf = 0; nf < 8; nf++)
                #pragma unroll
                for (int q = 0; q < 4; q++) c[mt][nf][q] = 0.f;

        #pragma unroll
        for (int ks = 0; ks < 4; ks++) {          // K16 steps
            const int u0 = ks * 8 + tig;
            uint32_t a[2][4], b[8][2];
            #pragma unroll
            for (int mt = 0; mt < 2; mt++) {
                int ra = moff + mt * 16 + g;
                a[mt][0] = uA[ra * UPITCH + u0];
                a[mt][1] = uA[(ra + 8) * UPITCH + u0];
                a[mt][2] = uA[ra * UPITCH + u0 + 4];
                a[mt][3] = uA[(ra + 8) * UPITCH + u0 + 4];
            }
            #pragma unroll
            for (int nf = 0; nf < 8; nf++) {
                int rb = noff + nf * 8 + g;
                b[nf][0] = sB[rb * UPITCH + u0];
                b[nf][1] = sB[rb * UPITCH + u0 + 4];
            }
            #pragma unroll
            for (int mt = 0; mt < 2; mt++)
                #pragma unroll
                for (int nf = 0; nf < 8; nf++)
                    mma_f16(c[mt][nf], a[mt], b[nf]);
        }

        // Epilogue: d2 = csq - 2*dot, top-3 insert.
        #pragma unroll
        for (int nf = 0; nf < 8; nf++) {
            int   cb  = t * 128 + noff + nf * 8 + 2 * tig;
            float cs0 = scsq[cb], cs1 = scsq[cb + 1];
            #pragma unroll
            for (int mt = 0; mt < 2; mt++) {
                const int s0 = mt * 2, s1 = mt * 2 + 1;
                ins3(fmaf(-2.f, c[mt][nf][0], cs0), cb,
                     m1[s0], m2[s0], m3[s0], i1[s0], i2[s0]);
                ins3(fmaf(-2.f, c[mt][nf][1], cs1), cb + 1,
                     m1[s0], m2[s0], m3[s0], i1[s0], i2[s0]);
                ins3(fmaf(-2.f, c[mt][nf][2], cs0), cb,
                     m1[s1], m2[s1], m3[s1], i1[s1], i2[s1]);
                ins3(fmaf(-2.f, c[mt][nf][3], cs1), cb + 1,
                     m1[s1], m2[s1], m3[s1], i1[s1], i2[s1]);
            }
        }

        if (t < 7) {   // store prefetched tile into the other buffer
            uint32_t* dst = uB + ((t + 1) & 1) * (128 * UPITCH);
            #pragma unroll
            for (int k = 0; k < 8; k++) {
                int idx = tid + 256 * k;
                int r = idx >> 4, c4 = idx & 15;
                uint2 u = make_uint2(packhf2(pf[k].x, pf[k].y),
                                     packhf2(pf[k].z, pf[k].w));
                *reinterpret_cast<uint2*>(&dst[r * UPITCH + c4 * 2]) = u;
            }
        }
        __syncthreads();
    }

    // Quad merge across tig lanes (same rows, different centroid columns).
    // Cross-lane m3 carries no index -> insert with -1 (escalated later).
    #pragma unroll
    for (int off = 1; off <= 2; off <<= 1) {
        #pragma unroll
        for (int s = 0; s < 4; s++) {
            float o1 = __shfl_xor_sync(0xffffffffu, m1[s], off);
            float o2 = __shfl_xor_sync(0xffffffffu, m2[s], off);
            float o3 = __shfl_xor_sync(0xffffffffu, m3[s], off);
            int   oi1 = __shfl_xor_sync(0xffffffffu, i1[s], off);
            int   oi2 = __shfl_xor_sync(0xffffffffu, i2[s], off);
            ins3(o1, oi1, m1[s], m2[s], m3[s], i1[s], i2[s]);
            ins3(o2, oi2, m1[s], m2[s], m3[s], i1[s], i2[s]);
            ins3(o3, -1,  m1[s], m2[s], m3[s], i1[s], i2[s]);
        }
    }
    const int half = wid & 1;
    if (tig == 0) {
        #pragma unroll
        for (int s = 0; s < 4; s++) {
            int row = moff + (s >> 1) * 16 + (s & 1) * 8 + g;
            sred1[half * 128 + row] = m1[s];
            sred2[half * 128 + row] = m2[s];
            sred3[half * 128 + row] = m3[s];
            sri1[half * 128 + row]  = i1[s];
            sri2[half * 128 + row]  = i2[s];
        }
    }
    __syncthreads();

    // Merge the two N-halves; classify; emit rescue work.
    if (tid < 128) {
        float M1 = sred1[tid], M2 = sred2[tid], M3 = sred3[tid];
        int   I1 = sri1[tid],  I2 = sri2[tid];
        ins3(sred1[128 + tid], sri1[128 + tid], M1, M2, M3, I1, I2);
        ins3(sred2[128 + tid], sri2[128 + tid], M1, M2, M3, I1, I2);
        ins3(sred3[128 + tid], -1,              M1, M2, M3, I1, I2);
        sbi[tid] = I1;

        bool amb   = (M2 - M1 < TAU);
        // Escalate when the certificate can't be trusted: 3rd-best inside TAU
        // OR the runner-up's identity was lost in a merge.
        bool fullf = (M3 - M1 < TAU) || (amb && I2 < 0);
        bool candf = amb && !fullf;

        unsigned balc = __ballot_sync(0xffffffffu, candf);
        if (balc) {
            int ldr = __ffs(balc) - 1;
            int base = 0;
            if (lane == ldr) base = atomicAdd(&g_ncand, __popc(balc));
            base = __shfl_sync(0xffffffffu, base, ldr);
            if (candf) {
                int pos = base + __popc(balc & ((1u << lane) - 1));
                g_cand[pos] = make_int4(vbase + tid, I1, I2, 0);
            }
        }
        unsigned balf = __ballot_sync(0xffffffffu, fullf);
        if (balf) {
            int ldr = __ffs(balf) - 1;
            int base = 0;
            if (lane == ldr) base = atomicAdd(&g_nfull, __popc(balf));
            base = __shfl_sync(0xffffffffu, base, ldr);
            if (fullf) {
                int pos = base + __popc(balf & ((1u << lane) - 1));
                g_full[pos] = vbase + tid;
            }
        }
    }
    __syncthreads();

    // Fused gather: coalesced write of (approx) winning centroid rows.
    // cand/full rows get overwritten by the follow-up kernels.
    #pragma unroll
    for (int k = 0; k < 8; k++) {
        int idx = tid + 256 * k;
        int r = idx >> 4, c4 = idx & 15;
        reinterpret_cast<float4*>(out)[(size_t)vbase * 16 + idx] =
            reinterpret_cast<const float4*>(cents)[sbi[r] * 16 + c4];
    }
}

// ---------------------------------------------------------------------------
// Kernel 2: exact fp32 check between the 2 certified candidates per row.
// ---------------------------------------------------------------------------
__global__ void cand_kernel(const float* __restrict__ vecs,
                            const float* __restrict__ cents,
                            float* __restrict__ out) {
    const int cnt = g_ncand;
    for (int idx = blockIdx.x * 256 + threadIdx.x; idx < cnt;
         idx += gridDim.x * 256) {
        int4 e = g_cand[idx];
        const float4* vr = reinterpret_cast<const float4*>(vecs) + (size_t)e.x * 16;
        float4 v[16];
        #pragma unroll
        for (int k = 0; k < 16; k++) v[k] = vr[k];

        int I1 = e.y, I2 = e.z;
        const float4* c1 = reinterpret_cast<const float4*>(cents) + I1 * 16;
        const float4* c2 = reinterpret_cast<const float4*>(cents) + I2 * 16;
        float a0 = 0.f, a1 = 0.f, b0 = 0.f, b1 = 0.f;
        #pragma unroll
        for (int k = 0; k < 16; k++) {
            float4 x = c1[k], y = c2[k];
            a0 = fmaf(v[k].x, x.x, a0); a1 = fmaf(v[k].y, x.y, a1);
            a0 = fmaf(v[k].z, x.z, a0); a1 = fmaf(v[k].w, x.w, a1);
            b0 = fmaf(v[k].x, y.x, b0); b1 = fmaf(v[k].y, y.y, b1);
            b0 = fmaf(v[k].z, y.z, b0); b1 = fmaf(v[k].w, y.w, b1);
        }
        float d1 = fmaf(-2.f, a0 + a1, g_csq[I1]);
        float d2 = fmaf(-2.f, b0 + b1, g_csq[I2]);
        int win = I1;
        if (d2 < d1 || (d2 == d1 && I2 < I1)) win = I2;

        const float4* cr = reinterpret_cast<const float4*>(cents) + win * 16;
        float4* orow = reinterpret_cast<float4*>(out) + (size_t)e.x * 16;
        #pragma unroll
        for (int k = 0; k < 16; k++) orow[k] = cr[k];
    }
}

// ---------------------------------------------------------------------------
// Kernel 3: block-tiled exact fp32 full rescan over g_full rows.
// 64 rows/block, 64-cent smem tiles (centroid reuse -> no L1 thrash);
// FFMA2 register-blocked 4x4 thread tiles.
// ---------------------------------------------------------------------------
#define FBM  64
#define PAD  68

__global__ __launch_bounds__(256, 2)
void full_kernel(const float* __restrict__ vecs,
                 const float* __restrict__ cents,
                 float* __restrict__ out) {
    const int cnt = g_nfull;
    if (blockIdx.x * FBM >= cnt) return;

    __shared__ float svec[FBM * PAD];
    __shared__ float scent[64 * PAD];
    __shared__ float scsq[64];
    __shared__ float sredd[16 * FBM];
    __shared__ int   sredi[16 * FBM];
    __shared__ int   srow[FBM];

    const int tid = threadIdx.x;
    const int tx  = tid & 15;
    const int ty  = tid >> 4;
    const int base = blockIdx.x * FBM;

    if (tid < FBM) {
        int p = base + tid;
        srow[tid] = g_full[p < cnt ? p : cnt - 1];
    }
    __syncthreads();

    #pragma unroll
    for (int k = 0; k < 4; k++) {
        int idx = tid + 256 * k;
        int r = idx >> 4, c4 = idx & 15;
        float4 val = reinterpret_cast<const float4*>(vecs)[(size_t)srow[r] * 16 + c4];
        *reinterpret_cast<float4*>(&svec[r * PAD + c4 * 4]) = val;
    }

    float bestd[4];
    int   besti[4];
    #pragma unroll
    for (int j = 0; j < 4; j++) { bestd[j] = 3.4e38f; besti[j] = 0; }

    for (int t = 0; t < NLMAX; t += 64) {
        __syncthreads();
        #pragma unroll
        for (int k = 0; k < 4; k++) {
            int idx = tid + 256 * k;
            int r = idx >> 4, c4 = idx & 15;
            float4 val = reinterpret_cast<const float4*>(cents)[(size_t)(t + r) * 16 + c4];
            *reinterpret_cast<float4*>(&scent[r * PAD + c4 * 4]) = val;
        }
        if (tid < 64) scsq[tid] = g_csq[t + tid];
        __syncthreads();

        u64 acc[4][4];
        #pragma unroll
        for (int j = 0; j < 4; j++)
            #pragma unroll
            for (int c = 0; c < 4; c++) acc[j][c] = 0ull;

        #pragma unroll
        for (int k4 = 0; k4 < DIM / 4; k4++) {
            ulonglong2 vv[4], cc[4];
            #pragma unroll
            for (int j = 0; j < 4; j++)
                vv[j] = *reinterpret_cast<const ulonglong2*>(
                            &svec[(tx + 16 * j) * PAD + k4 * 4]);
            #pragma unroll
            for (int c = 0; c < 4; c++)
                cc[c] = *reinterpret_cast<const ulonglong2*>(
                            &scent[(ty + 16 * c) * PAD + k4 * 4]);
            #pragma unroll
            for (int j = 0; j < 4; j++)
                #pragma unroll
                for (int c = 0; c < 4; c++) {
                    acc[j][c] = ffma2(vv[j].x, cc[c].x, acc[j][c]);
                    acc[j][c] = ffma2(vv[j].y, cc[c].y, acc[j][c]);
                }
        }

        #pragma unroll
        for (int c = 0; c < 4; c++) {
            int   ci = t + ty + 16 * c;
            float cs = scsq[ty + 16 * c];
            #pragma unroll
            for (int j = 0; j < 4; j++) {
                float2 f  = unpack2(acc[j][c]);
                float  d2 = fmaf(-2.f, f.x + f.y, cs);
                if (d2 < bestd[j]) { bestd[j] = d2; besti[j] = ci; }
            }
        }
    }

    #pragma unroll
    for (int j = 0; j < 4; j++) {
        int v = tx + 16 * j;
        sredd[ty * FBM + v] = bestd[j];
        sredi[ty * FBM + v] = besti[j];
    }
    __syncthreads();
    if (tid < FBM) {
        float bd = sredd[tid];
        int   bi2 = sredi[tid];
        #pragma unroll
        for (int r = 1; r < 16; r++) {
            float d  = sredd[r * FBM + tid];
            int   i2 = sredi[r * FBM + tid];
            if (d < bd || (d == bd && i2 < bi2)) { bd = d; bi2 = i2; }
        }
        sredi[tid] = bi2;           // winner table (row 0 reused)
    }
    __syncthreads();

    #pragma unroll
    for (int k = 0; k < 4; k++) {
        int idx = tid + 256 * k;
        int r = idx >> 4, c4 = idx & 15;
        reinterpret_cast<float4*>(out)[(size_t)srow[r] * 16 + c4] =
            reinterpret_cast<const float4*>(cents)[sredi[r] * 16 + c4];
    }
}

// ---------------------------------------------------------------------------
extern "C" void kernel_launch(void* const* d_in, const int* in_sizes, int n_in,
                              void* d_out, int out_size) {
    const float* vecs  = (const float*)d_in[0];
    const float* cents = (const float*)d_in[1];
    float*       out   = (float*)d_out;

    const int n = in_sizes[0] / DIM;   // 262144

    cudaFuncSetAttribute(assign_mma_kernel,
                         cudaFuncAttributeMaxDynamicSharedMemorySize, SMEMB);

    csq_kernel<<<128, 256>>>(cents);
    assign_mma_kernel<<<n / 128, 256, SMEMB>>>(vecs, cents, out);
    cand_kernel<<<256, 256>>>(vecs, cents, out);
    full_kernel<<<NMAX / FBM, 256>>>(vecs, cents, out);
}

// round 17
// speedup vs baseline: 2.2777x; 2.2777x over previous
#include <cuda_runtime.h>
#include <cuda_fp16.h>
#include <cstdint>

#define DIM     64
#define NMAX    262144
#define NLMAX   1024
#define TAU     0.3f
#define UPITCH  36          // uints per f16 tile row: 32 data + 4 pad (bank-clean)

__device__ float g_csq[NLMAX];
__device__ int   g_nrescue;
__device__ int   g_rescue[NMAX];

typedef unsigned long long u64;

// Packed fp32x2 FMA (FFMA2) for the exact rescue pass.
__device__ __forceinline__ u64 ffma2(u64 a, u64 b, u64 c) {
    u64 d;
    asm("fma.rn.f32x2 %0, %1, %2, %3;" : "=l"(d) : "l"(a), "l"(b), "l"(c));
    return d;
}
__device__ __forceinline__ float2 unpack2(u64 v) {
    float2 f;
    asm("mov.b64 {%0, %1}, %2;" : "=f"(f.x), "=f"(f.y) : "l"(v));
    return f;
}

// fp16 tensor-core MMA, m16n8k16 with fp32 accumulate.
__device__ __forceinline__ void mma_f16(float c[4], const uint32_t a[4],
                                        const uint32_t b[2]) {
    asm volatile(
        "mma.sync.aligned.m16n8k16.row.col.f32.f16.f16.f32 "
        "{%0,%1,%2,%3}, {%4,%5,%6,%7}, {%8,%9}, {%0,%1,%2,%3};"
        : "+f"(c[0]), "+f"(c[1]), "+f"(c[2]), "+f"(c[3])
        : "r"(a[0]), "r"(a[1]), "r"(a[2]), "r"(a[3]), "r"(b[0]), "r"(b[1]));
}

__device__ __forceinline__ uint32_t packhf2(float x, float y) {
    __half2 h = __floats2half2_rn(x, y);
    return *reinterpret_cast<uint32_t*>(&h);
}

// ---------------------------------------------------------------------------
// Kernel 0: centroid squared norms (warp per row) + counter reset.
// ---------------------------------------------------------------------------
__global__ void csq_kernel(const float* __restrict__ cents) {
    if (blockIdx.x == 0 && threadIdx.x == 0) g_nrescue = 0;
    int w    = (blockIdx.x * blockDim.x + threadIdx.x) >> 5;
    int lane = threadIdx.x & 31;
    if (w < NLMAX) {
        float2 v = reinterpret_cast<const float2*>(cents + (size_t)w * DIM)[lane];
        float s = v.x * v.x + v.y * v.y;
        #pragma unroll
        for (int off = 16; off > 0; off >>= 1)
            s += __shfl_xor_sync(0xffffffffu, s, off);
        if (lane == 0) g_csq[w] = s;
    }
}

// ---------------------------------------------------------------------------
// Kernel 1: fp16 mma.sync assignment + top-2 margins + fused gather.
// (Round-11 champion, unchanged.) Ambiguous rows -> g_rescue.
// ---------------------------------------------------------------------------
#define UA_OFF   0
#define UB_OFF   18432               // two buffers of 128*36*4 B
#define SCSQ_OFF 55296
#define RED1_OFF 59392               // float [2][128]
#define RED2_OFF 60416               // float [2][128]
#define REDI_OFF 61440               // int   [2][128]
#define SBI_OFF  62464               // int   [128]
#define SMEMB    62976

__global__ __launch_bounds__(256, 2)
void assign_mma_kernel(const float* __restrict__ vecs,
                       const float* __restrict__ cents,
                       float* __restrict__ out) {
    extern __shared__ char smem[];
    uint32_t* uA    = reinterpret_cast<uint32_t*>(smem + UA_OFF);
    uint32_t* uB    = reinterpret_cast<uint32_t*>(smem + UB_OFF);
    float*    scsq  = reinterpret_cast<float*>(smem + SCSQ_OFF);
    float*    sred1 = reinterpret_cast<float*>(smem + RED1_OFF);
    float*    sred2 = reinterpret_cast<float*>(smem + RED2_OFF);
    int*      sredi = reinterpret_cast<int*>(smem + REDI_OFF);
    int*      sbi   = reinterpret_cast<int*>(smem + SBI_OFF);

    const int tid  = threadIdx.x;
    const int lane = tid & 31;
    const int wid  = tid >> 5;
    const int g    = lane >> 2;
    const int tig  = lane & 3;
    const int moff = (wid >> 1) * 32;
    const int noff = (wid & 1) * 64;
    const int vbase = blockIdx.x * 128;

    // A tile: fp32 -> f16x2, padded rows (UPITCH=36 -> conflict-free frags).
    #pragma unroll
    for (int k = 0; k < 8; k++) {
        int idx = tid + 256 * k;
        int r = idx >> 4, c4 = idx & 15;
        float4 v = reinterpret_cast<const float4*>(vecs)[(size_t)(vbase + r) * 16 + c4];
        uint2 u = make_uint2(packhf2(v.x, v.y), packhf2(v.z, v.w));
        *reinterpret_cast<uint2*>(&uA[r * UPITCH + c4 * 2]) = u;
    }
    float4 pf[8];
    #pragma unroll
    for (int k = 0; k < 8; k++) {
        int idx = tid + 256 * k;
        int r = idx >> 4, c4 = idx & 15;
        pf[k] = reinterpret_cast<const float4*>(cents)[(size_t)r * 16 + c4];
    }
    #pragma unroll
    for (int k = 0; k < 4; k++) scsq[tid + 256 * k] = g_csq[tid + 256 * k];
    #pragma unroll
    for (int k = 0; k < 8; k++) {
        int idx = tid + 256 * k;
        int r = idx >> 4, c4 = idx & 15;
        uint2 u = make_uint2(packhf2(pf[k].x, pf[k].y), packhf2(pf[k].z, pf[k].w));
        *reinterpret_cast<uint2*>(&uB[r * UPITCH + c4 * 2]) = u;
    }
    __syncthreads();

    float m1[4], m2[4];
    int   bi[4];
    #pragma unroll
    for (int s = 0; s < 4; s++) { m1[s] = 3.4e38f; m2[s] = 3.4e38f; bi[s] = 0; }

    for (int t = 0; t < 8; t++) {
        if (t < 7) {
            #pragma unroll
            for (int k = 0; k < 8; k++) {
                int idx = tid + 256 * k;
                int r = idx >> 4, c4 = idx & 15;
                pf[k] = reinterpret_cast<const float4*>(cents)
                            [(size_t)((t + 1) * 128 + r) * 16 + c4];
            }
        }

        const uint32_t* sB = uB + (t & 1) * (128 * UPITCH);

        float c[2][8][4];
        #pragma unroll
        for (int mt = 0; mt < 2; mt++)
            #pragma unroll
            for (int nf = 0; nf < 8; nf++)
                #pragma unroll
                for (int q = 0; q < 4; q++) c[mt][nf][q] = 0.f;

        #pragma unroll
        for (int ks = 0; ks < 4; ks++) {
            const int u0 = ks * 8 + tig;
            uint32_t a[2][4], b[8][2];
            #pragma unroll
            for (int mt = 0; mt < 2; mt++) {
                int ra = moff + mt * 16 + g;
                a[mt][0] = uA[ra * UPITCH + u0];
                a[mt][1] = uA[(ra + 8) * UPITCH + u0];
                a[mt][2] = uA[ra * UPITCH + u0 + 4];
                a[mt][3] = uA[(ra + 8) * UPITCH + u0 + 4];
            }
            #pragma unroll
            for (int nf = 0; nf < 8; nf++) {
                int rb = noff + nf * 8 + g;
                b[nf][0] = sB[rb * UPITCH + u0];
                b[nf][1] = sB[rb * UPITCH + u0 + 4];
            }
            #pragma unroll
            for (int mt = 0; mt < 2; mt++)
                #pragma unroll
                for (int nf = 0; nf < 8; nf++)
                    mma_f16(c[mt][nf], a[mt], b[nf]);
        }

        #pragma unroll
        for (int nf = 0; nf < 8; nf++) {
            int   cb  = t * 128 + noff + nf * 8 + 2 * tig;
            float cs0 = scsq[cb], cs1 = scsq[cb + 1];
            #pragma unroll
            for (int mt = 0; mt < 2; mt++) {
                const int s0 = mt * 2, s1 = mt * 2 + 1;
                float d;
                d = fmaf(-2.f, c[mt][nf][0], cs0);
                if (d < m1[s0]) { m2[s0] = m1[s0]; m1[s0] = d; bi[s0] = cb; }
                else            { m2[s0] = fminf(m2[s0], d); }
                d = fmaf(-2.f, c[mt][nf][1], cs1);
                if (d < m1[s0]) { m2[s0] = m1[s0]; m1[s0] = d; bi[s0] = cb + 1; }
                else            { m2[s0] = fminf(m2[s0], d); }
                d = fmaf(-2.f, c[mt][nf][2], cs0);
                if (d < m1[s1]) { m2[s1] = m1[s1]; m1[s1] = d; bi[s1] = cb; }
                else            { m2[s1] = fminf(m2[s1], d); }
                d = fmaf(-2.f, c[mt][nf][3], cs1);
                if (d < m1[s1]) { m2[s1] = m1[s1]; m1[s1] = d; bi[s1] = cb + 1; }
                else            { m2[s1] = fminf(m2[s1], d); }
            }
        }

        if (t < 7) {
            uint32_t* dst = uB + ((t + 1) & 1) * (128 * UPITCH);
            #pragma unroll
            for (int k = 0; k < 8; k++) {
                int idx = tid + 256 * k;
                int r = idx >> 4, c4 = idx & 15;
                uint2 u = make_uint2(packhf2(pf[k].x, pf[k].y),
                                     packhf2(pf[k].z, pf[k].w));
                *reinterpret_cast<uint2*>(&dst[r * UPITCH + c4 * 2]) = u;
            }
        }
        __syncthreads();
    }

    #pragma unroll
    for (int off = 1; off <= 2; off <<= 1) {
        #pragma unroll
        for (int s = 0; s < 4; s++) {
            float om1 = __shfl_xor_sync(0xffffffffu, m1[s], off);
            float om2 = __shfl_xor_sync(0xffffffffu, m2[s], off);
            int   oi  = __shfl_xor_sync(0xffffffffu, bi[s], off);
            bool better = (om1 < m1[s]) || (om1 == m1[s] && oi < bi[s]);
            m2[s] = fminf(fminf(m2[s], om2), fmaxf(m1[s], om1));
            m1[s] = fminf(m1[s], om1);
            if (better) bi[s] = oi;
        }
    }
    const int half = wid & 1;
    if (tig == 0) {
        #pragma unroll
        for (int s = 0; s < 4; s++) {
            int row = moff + (s >> 1) * 16 + (s & 1) * 8 + g;
            sred1[half * 128 + row] = m1[s];
            sred2[half * 128 + row] = m2[s];
            sredi[half * 128 + row] = bi[s];
        }
    }
    __syncthreads();
    if (tid < 128) {
        float a1 = sred1[tid],   b1 = sred1[128 + tid];
        float a2 = sred2[tid],   b2 = sred2[128 + tid];
        int   ai = sredi[tid],   bx = sredi[128 + tid];
        bool  bb = (b1 < a1) || (b1 == a1 && bx < ai);
        float g1 = fminf(a1, b1);
        float g2 = fminf(fminf(a2, b2), fmaxf(a1, b1));
        sbi[tid] = bb ? bx : ai;
        if (g2 - g1 < TAU) {
            int p = atomicAdd(&g_nrescue, 1);
            g_rescue[p] = vbase + tid;
        }
    }
    __syncthreads();

    // Fused gather: coalesced write of (approx) winning centroid rows.
    #pragma unroll
    for (int k = 0; k < 8; k++) {
        int idx = tid + 256 * k;
        int r = idx >> 4, c4 = idx & 15;
        reinterpret_cast<float4*>(out)[(size_t)vbase * 16 + idx] =
            reinterpret_cast<const float4*>(cents)[sbi[r] * 16 + c4];
    }
}

// ---------------------------------------------------------------------------
// Kernel 2: block-tiled exact fp32 full rescan over g_rescue rows.
// 64 rows/block, 64-cent smem tiles (centroid reuse -> no L1 thrash);
// FFMA2 register-blocked 4x4 thread tiles. Overwrites resolved rows.
// ---------------------------------------------------------------------------
#define FBM  64
#define PAD  68

__global__ __launch_bounds__(256, 2)
void rescue_kernel(const float* __restrict__ vecs,
                   const float* __restrict__ cents,
                   float* __restrict__ out) {
    const int cnt = g_nrescue;
    if (blockIdx.x * FBM >= cnt) return;

    __shared__ float svec[FBM * PAD];
    __shared__ float scent[64 * PAD];
    __shared__ float scsq[64];
    __shared__ float sredd[16 * FBM];
    __shared__ int   sredi[16 * FBM];
    __shared__ int   srow[FBM];

    const int tid = threadIdx.x;
    const int tx  = tid & 15;
    const int ty  = tid >> 4;
    const int base = blockIdx.x * FBM;

    if (tid < FBM) {
        int p = base + tid;
        srow[tid] = g_rescue[p < cnt ? p : cnt - 1];
    }
    __syncthreads();

    #pragma unroll
    for (int k = 0; k < 4; k++) {
        int idx = tid + 256 * k;
        int r = idx >> 4, c4 = idx & 15;
        float4 val = reinterpret_cast<const float4*>(vecs)[(size_t)srow[r] * 16 + c4];
        *reinterpret_cast<float4*>(&svec[r * PAD + c4 * 4]) = val;
    }

    float bestd[4];
    int   besti[4];
    #pragma unroll
    for (int j = 0; j < 4; j++) { bestd[j] = 3.4e38f; besti[j] = 0; }

    for (int t = 0; t < NLMAX; t += 64) {
        __syncthreads();
        #pragma unroll
        for (int k = 0; k < 4; k++) {
            int idx = tid + 256 * k;
            int r = idx >> 4, c4 = idx & 15;
            float4 val = reinterpret_cast<const float4*>(cents)[(size_t)(t + r) * 16 + c4];
            *reinterpret_cast<float4*>(&scent[r * PAD + c4 * 4]) = val;
        }
        if (tid < 64) scsq[tid] = g_csq[t + tid];
        __syncthreads();

        u64 acc[4][4];
        #pragma unroll
        for (int j = 0; j < 4; j++)
            #pragma unroll
            for (int c = 0; c < 4; c++) acc[j][c] = 0ull;

        #pragma unroll
        for (int k4 = 0; k4 < DIM / 4; k4++) {
            ulonglong2 vv[4], cc[4];
            #pragma unroll
            for (int j = 0; j < 4; j++)
                vv[j] = *reinterpret_cast<const ulonglong2*>(
                            &svec[(tx + 16 * j) * PAD + k4 * 4]);
            #pragma unroll
            for (int c = 0; c < 4; c++)
                cc[c] = *reinterpret_cast<const ulonglong2*>(
                            &scent[(ty + 16 * c) * PAD + k4 * 4]);
            #pragma unroll
            for (int j = 0; j < 4; j++)
                #pragma unroll
                for (int c = 0; c < 4; c++) {
                    acc[j][c] = ffma2(vv[j].x, cc[c].x, acc[j][c]);
                    acc[j][c] = ffma2(vv[j].y, cc[c].y, acc[j][c]);
                }
        }

        #pragma unroll
        for (int c = 0; c < 4; c++) {
            int   ci = t + ty + 16 * c;
            float cs = scsq[ty + 16 * c];
            #pragma unroll
            for (int j = 0; j < 4; j++) {
                float2 f  = unpack2(acc[j][c]);
                float  d2 = fmaf(-2.f, f.x + f.y, cs);
                if (d2 < bestd[j]) { bestd[j] = d2; besti[j] = ci; }
            }
        }
    }

    #pragma unroll
    for (int j = 0; j < 4; j++) {
        int v = tx + 16 * j;
        sredd[ty * FBM + v] = bestd[j];
        sredi[ty * FBM + v] = besti[j];
    }
    __syncthreads();
    if (tid < FBM) {
        float bd = sredd[tid];
        int   bi2 = sredi[tid];
        #pragma unroll
        for (int r = 1; r < 16; r++) {
            float d  = sredd[r * FBM + tid];
            int   i2 = sredi[r * FBM + tid];
            if (d < bd || (d == bd && i2 < bi2)) { bd = d; bi2 = i2; }
        }
        sredi[tid] = bi2;           // winner table (row 0 reused)
    }
    __syncthreads();

    #pragma unroll
    for (int k = 0; k < 4; k++) {
        int idx = tid + 256 * k;
        int r = idx >> 4, c4 = idx & 15;
        reinterpret_cast<float4*>(out)[(size_t)srow[r] * 16 + c4] =
            reinterpret_cast<const float4*>(cents)[sredi[r] * 16 + c4];
    }
}

// ---------------------------------------------------------------------------
extern "C" void kernel_launch(void* const* d_in, const int* in_sizes, int n_in,
                              void* d_out, int out_size) {
    const float* vecs  = (const float*)d_in[0];
    const float* cents = (const float*)d_in[1];
    float*       out   = (float*)d_out;

    const int n = in_sizes[0] / DIM;   // 262144

    cudaFuncSetAttribute(assign_mma_kernel,
                         cudaFuncAttributeMaxDynamicSharedMemorySize, SMEMB);

    csq_kernel<<<128, 256>>>(cents);
    assign_mma_kernel<<<n / 128, 256, SMEMB>>>(vecs, cents, out);
    rescue_kernel<<<NMAX / FBM, 256>>>(vecs, cents, out);
}